// round 13
// baseline (speedup 1.0000x reference)
#include <cuda_runtime.h>
#include <cuda_fp16.h>
#include <cstdint>

#define KDIM 4096
#define NDIM 11008
#define MDIM 4096
#define BM 128
#define BN 128
#define BK 64
#define STRIDE 72                 // padded row stride in halves (144 B)
#define STAGE_ELEMS (128 * STRIDE)
#define SMEM_BYTES (4 * STAGE_ELEMS * 2)   // A0,A1,B0,B1 = 73728 B -> 2 CTAs/SM
#define NUM_KT (KDIM / BK)        // 64

// fp16 copy of x (harness provides float32 for the reference's float16 tensors)
__device__ __half g_xh[(size_t)MDIM * KDIM];

// 8 floats per thread: 2x float4 load, 1x uint4 store
__global__ void cvt_x_kernel(const float* __restrict__ x) {
    // allow the dependent GEMM kernel to begin its cvt-independent prologue
    asm volatile("griddepcontrol.launch_dependents;");
    size_t i = ((size_t)blockIdx.x * blockDim.x + threadIdx.x) * 8;
    float4 v0 = *(const float4*)(x + i);
    float4 v1 = *(const float4*)(x + i + 4);
    __half2 h0 = __floats2half2_rn(v0.x, v0.y);
    __half2 h1 = __floats2half2_rn(v0.z, v0.w);
    __half2 h2 = __floats2half2_rn(v1.x, v1.y);
    __half2 h3 = __floats2half2_rn(v1.z, v1.w);
    uint4 st;
    st.x = *(uint32_t*)&h0;
    st.y = *(uint32_t*)&h1;
    st.z = *(uint32_t*)&h2;
    st.w = *(uint32_t*)&h3;
    *(uint4*)(g_xh + i) = st;
}

__device__ __forceinline__ void cp_async16(uint32_t saddr, const void* gptr) {
    asm volatile("cp.async.cg.shared.global [%0], [%1], 16;\n" :: "r"(saddr), "l"(gptr));
}
__device__ __forceinline__ void cp_commit() { asm volatile("cp.async.commit_group;\n"); }
__device__ __forceinline__ void cp_wait0()  { asm volatile("cp.async.wait_group 0;\n"); }

__device__ __forceinline__ void ldmatrix_x4(uint32_t& r0, uint32_t& r1, uint32_t& r2, uint32_t& r3, uint32_t addr) {
    asm volatile("ldmatrix.sync.aligned.m8n8.x4.shared.b16 {%0,%1,%2,%3}, [%4];\n"
                 : "=r"(r0), "=r"(r1), "=r"(r2), "=r"(r3) : "r"(addr));
}

__device__ __forceinline__ void mma16816(float* d, const uint32_t* a, const uint32_t* b) {
    asm volatile(
        "mma.sync.aligned.m16n8k16.row.col.f32.f16.f16.f32 "
        "{%0,%1,%2,%3}, {%4,%5,%6,%7}, {%8,%9}, {%0,%1,%2,%3};\n"
        : "+f"(d[0]), "+f"(d[1]), "+f"(d[2]), "+f"(d[3])
        : "r"(a[0]), "r"(a[1]), "r"(a[2]), "r"(a[3]), "r"(b[0]), "r"(b[1]));
}

__global__ __launch_bounds__(256, 2)
void qlinear_kernel(const int*   __restrict__ packed,
                    const float* __restrict__ scales,
                    const float* __restrict__ bias,
                    float*       __restrict__ out)
{
    extern __shared__ __half smem[];
    const uint32_t smem_base = (uint32_t)__cvta_generic_to_shared(smem);

    const int tid  = threadIdx.x;
    const int lane = tid & 31;
    const int warp = tid >> 5;
    const int wm   = warp & 1;    // 2 warps along M (64 rows each)
    const int wn   = warp >> 1;   // 4 warps along N (32 cols each)

    const int bm = blockIdx.y * BM;
    const int bn = blockIdx.x * BN;

    // ---- B dequant mapping: thread owns one n (tid&127) and 4 k-words ----
    const int b_n  = tid & 127;          // n within tile
    const int kw0  = tid >> 7;           // 0 or 1; kw = kw0 + 2*i
    const int n_g  = bn + b_n;           // global n for this thread's B work

    const __half2 off1032 = __halves2half2(__ushort_as_half((unsigned short)0x6408),
                                           __ushort_as_half((unsigned short)0x6408));

    float acc[4][4][4];
#pragma unroll
    for (int i = 0; i < 4; i++)
#pragma unroll
        for (int j = 0; j < 4; j++)
#pragma unroll
            for (int k = 0; k < 4; k++) acc[i][j][k] = 0.f;

    auto a_saddr = [&](int stage, int row, int colbytes) -> uint32_t {
        return smem_base + (uint32_t)((stage * STAGE_ELEMS + row * STRIDE) * 2) + colbytes;
    };
    auto b_saddr = [&](int stage, int row, int colbytes) -> uint32_t {
        return smem_base + (uint32_t)(((2 + stage) * STAGE_ELEMS + row * STRIDE) * 2) + colbytes;
    };

    uint32_t bw[4];
    __half   sc;

    // ---------- prologue ----------
    {
        // B stage 0 first: does NOT depend on cvt_x output (reads packed/scales only)
#pragma unroll
        for (int i = 0; i < 4; i++) {
            int kw = kw0 + 2 * i;
            bw[i] = (uint32_t)packed[(size_t)kw * NDIM + n_g];
        }
        sc = __float2half_rn(scales[n_g]);  // group 0
        __half2 sc2 = __half2half2(sc);
        uint32_t sbase = b_saddr(0, b_n, 0);
#pragma unroll
        for (int i = 0; i < 4; i++) {
            int kw = kw0 + 2 * i;
            uint32_t w = bw[i];
            uint32_t r[4];
#pragma unroll
            for (int j = 0; j < 4; j++) {
                uint32_t v = w >> (8 * j);
                uint32_t p = ((v & 0xFu) | ((v & 0xF0u) << 12)) | 0x64006400u;
                __half2 h = __hmul2(__hsub2(*(__half2*)&p, off1032), sc2);
                r[j] = *(uint32_t*)&h;
            }
            asm volatile("st.shared.v4.b32 [%0], {%1,%2,%3,%4};\n"
                         :: "r"(sbase + kw * 16), "r"(r[0]), "r"(r[1]), "r"(r[2]), "r"(r[3]));
        }

        // Now wait for cvt_x to fully complete before touching g_xh
        asm volatile("griddepcontrol.wait;" ::: "memory");

#pragma unroll
        for (int i = 0; i < 4; i++) {
            int c = tid + 256 * i;
            int row = c >> 3, cc = c & 7;
            cp_async16(a_saddr(0, row, cc * 16),
                       g_xh + (size_t)(bm + row) * KDIM + cc * 8);
        }
        cp_commit();
        cp_wait0();
        __syncthreads();
    }

    // ---------- main loop ----------
    const int arow  = wm * 64 + (lane & 15);
    const int acolg = (lane >> 4) * 8;
    const int brow  = wn * 32 + (lane & 15);

    for (int kt = 0; kt < NUM_KT; ++kt) {
        const int buf = kt & 1;
        const bool has_next = (kt + 1) < NUM_KT;

        if (has_next) {
            const int kb = (kt + 1) * BK;
#pragma unroll
            for (int i = 0; i < 4; i++) {
                int c = tid + 256 * i;
                int row = c >> 3, cc = c & 7;
                cp_async16(a_saddr(buf ^ 1, row, cc * 16),
                           g_xh + (size_t)(bm + row) * KDIM + kb + cc * 8);
            }
            cp_commit();
#pragma unroll
            for (int i = 0; i < 4; i++) {
                int kw = kw0 + 2 * i;
                bw[i] = (uint32_t)packed[(size_t)((kt + 1) * 8 + kw) * NDIM + n_g];
            }
            sc = __float2half_rn(scales[(size_t)((kt + 1) >> 1) * NDIM + n_g]);
        }

        // ---- compute from buf ----
        const uint32_t abase = smem_base + (uint32_t)(buf * STAGE_ELEMS * 2);
        const uint32_t bbase = smem_base + (uint32_t)((2 + buf) * STAGE_ELEMS * 2);
#pragma unroll
        for (int ks = 0; ks < 4; ks++) {
            uint32_t a[4][4];
#pragma unroll
            for (int mt = 0; mt < 4; mt++) {
                uint32_t addr = abase + (uint32_t)(((arow + mt * 16) * STRIDE + ks * 16 + acolg) * 2);
                ldmatrix_x4(a[mt][0], a[mt][1], a[mt][2], a[mt][3], addr);
            }
            uint32_t b[4][2];
#pragma unroll
            for (int nt2 = 0; nt2 < 2; nt2++) {
                uint32_t r0, r1, r2, r3;
                uint32_t addr = bbase + (uint32_t)(((brow + nt2 * 16) * STRIDE + ks * 16 + acolg) * 2);
                ldmatrix_x4(r0, r1, r2, r3, addr);
                b[2 * nt2][0] = r0; b[2 * nt2][1] = r2;
                b[2 * nt2 + 1][0] = r1; b[2 * nt2 + 1][1] = r3;
            }
#pragma unroll
            for (int mt = 0; mt < 4; mt++)
#pragma unroll
                for (int nt = 0; nt < 4; nt++)
                    mma16816(acc[mt][nt], a[mt], b[nt]);
        }

        if (has_next) {
            __half2 sc2 = __half2half2(sc);
            uint32_t sbase = b_saddr(buf ^ 1, b_n, 0);
#pragma unroll
            for (int i = 0; i < 4; i++) {
                int kw = kw0 + 2 * i;
                uint32_t w = bw[i];
                uint32_t r[4];
#pragma unroll
                for (int j = 0; j < 4; j++) {
                    uint32_t v = w >> (8 * j);
                    uint32_t p = ((v & 0xFu) | ((v & 0xF0u) << 12)) | 0x64006400u;
                    __half2 h = __hmul2(__hsub2(*(__half2*)&p, off1032), sc2);
                    r[j] = *(uint32_t*)&h;
                }
                asm volatile("st.shared.v4.b32 [%0], {%1,%2,%3,%4};\n"
                             :: "r"(sbase + kw * 16), "r"(r[0]), "r"(r[1]), "r"(r[2]), "r"(r[3]));
            }
            cp_wait0();
        }
        __syncthreads();
    }

    // ---------- epilogue: f32 out, rounded through fp16 to match reference ----------
#pragma unroll
    for (int mt = 0; mt < 4; mt++) {
#pragma unroll
        for (int nt = 0; nt < 4; nt++) {
            int row0 = bm + wm * 64 + mt * 16 + (lane >> 2);
            int col  = bn + wn * 32 + nt * 8 + (lane & 3) * 2;
            float2 bf = *(const float2*)(bias + col);
            float2 v0, v1;
            v0.x = __half2float(__float2half_rn(acc[mt][nt][0] + bf.x));
            v0.y = __half2float(__float2half_rn(acc[mt][nt][1] + bf.y));
            v1.x = __half2float(__float2half_rn(acc[mt][nt][2] + bf.x));
            v1.y = __half2float(__float2half_rn(acc[mt][nt][3] + bf.y));
            *(float2*)(out + (size_t)row0 * NDIM + col) = v0;
            *(float2*)(out + (size_t)(row0 + 8) * NDIM + col) = v1;
        }
    }
}

extern "C" void kernel_launch(void* const* d_in, const int* in_sizes, int n_in,
                              void* d_out, int out_size) {
    const float* x      = (const float*)d_in[0];
    const int*   packed = (const int*)d_in[1];
    const float* scales = (const float*)d_in[2];
    const float* bias   = (const float*)d_in[3];
    float*       out    = (float*)d_out;

    // prepass: x (f32) -> g_xh (fp16); signals dependents at entry
    const size_t n_x = (size_t)MDIM * KDIM;
    cvt_x_kernel<<<(unsigned)(n_x / 8 / 256), 256>>>(x);

    cudaFuncSetAttribute(qlinear_kernel, cudaFuncAttributeMaxDynamicSharedMemorySize, SMEM_BYTES);

    // GEMM launched as a programmatic dependent of cvt_x: its B-prologue
    // (packed/scales only) overlaps cvt_x's tail; griddepcontrol.wait guards g_xh.
    cudaLaunchConfig_t cfg = {};
    cfg.gridDim = dim3(NDIM / BN, MDIM / BM, 1);
    cfg.blockDim = dim3(256, 1, 1);
    cfg.dynamicSmemBytes = SMEM_BYTES;
    cfg.stream = 0;
    cudaLaunchAttribute attr[1];
    attr[0].id = cudaLaunchAttributeProgrammaticStreamSerialization;
    attr[0].val.programmaticStreamSerializationAllowed = 1;
    cfg.attrs = attr;
    cfg.numAttrs = 1;
    cudaLaunchKernelEx(&cfg, qlinear_kernel, packed, scales, bias, out);
}

// round 14
// speedup vs baseline: 1.0004x; 1.0004x over previous
#include <cuda_runtime.h>
#include <cuda_fp16.h>
#include <cstdint>

#define KDIM 4096
#define NDIM 11008
#define MDIM 4096
#define BM 128
#define BN 128
#define BK 64
#define STRIDE 72                 // padded row stride in halves (144 B)
#define STAGE_ELEMS (128 * STRIDE)
#define SMEM_BYTES (4 * STAGE_ELEMS * 2)   // A0,A1,B0,B1 = 73728 B -> 2 CTAs/SM
#define NUM_KT (KDIM / BK)        // 64

// fp16 copy of x (harness provides float32 for the reference's float16 tensors)
__device__ __half g_xh[(size_t)MDIM * KDIM];

// 8 floats per thread: 2x float4 load, 1x uint4 store
__global__ void cvt_x_kernel(const float* __restrict__ x) {
    // allow the dependent GEMM kernel to begin its cvt-independent prologue
    asm volatile("griddepcontrol.launch_dependents;");
    size_t i = ((size_t)blockIdx.x * blockDim.x + threadIdx.x) * 8;
    float4 v0 = *(const float4*)(x + i);
    float4 v1 = *(const float4*)(x + i + 4);
    __half2 h0 = __floats2half2_rn(v0.x, v0.y);
    __half2 h1 = __floats2half2_rn(v0.z, v0.w);
    __half2 h2 = __floats2half2_rn(v1.x, v1.y);
    __half2 h3 = __floats2half2_rn(v1.z, v1.w);
    uint4 st;
    st.x = *(uint32_t*)&h0;
    st.y = *(uint32_t*)&h1;
    st.z = *(uint32_t*)&h2;
    st.w = *(uint32_t*)&h3;
    *(uint4*)(g_xh + i) = st;
}

__device__ __forceinline__ void cp_async16(uint32_t saddr, const void* gptr) {
    asm volatile("cp.async.cg.shared.global [%0], [%1], 16;\n" :: "r"(saddr), "l"(gptr));
}
__device__ __forceinline__ void cp_commit() { asm volatile("cp.async.commit_group;\n"); }
__device__ __forceinline__ void cp_wait0()  { asm volatile("cp.async.wait_group 0;\n"); }

__device__ __forceinline__ void ldmatrix_x4(uint32_t& r0, uint32_t& r1, uint32_t& r2, uint32_t& r3, uint32_t addr) {
    asm volatile("ldmatrix.sync.aligned.m8n8.x4.shared.b16 {%0,%1,%2,%3}, [%4];\n"
                 : "=r"(r0), "=r"(r1), "=r"(r2), "=r"(r3) : "r"(addr));
}

__device__ __forceinline__ void mma16816(float* d, const uint32_t* a, const uint32_t* b) {
    asm volatile(
        "mma.sync.aligned.m16n8k16.row.col.f32.f16.f16.f32 "
        "{%0,%1,%2,%3}, {%4,%5,%6,%7}, {%8,%9}, {%0,%1,%2,%3};\n"
        : "+f"(d[0]), "+f"(d[1]), "+f"(d[2]), "+f"(d[3])
        : "r"(a[0]), "r"(a[1]), "r"(a[2]), "r"(a[3]), "r"(b[0]), "r"(b[1]));
}

__global__ __launch_bounds__(256, 2)
void qlinear_kernel(const int*   __restrict__ packed,
                    const float* __restrict__ scales,
                    const float* __restrict__ bias,
                    float*       __restrict__ out)
{
    extern __shared__ __half smem[];
    const uint32_t smem_base = (uint32_t)__cvta_generic_to_shared(smem);

    const int tid  = threadIdx.x;
    const int lane = tid & 31;
    const int warp = tid >> 5;
    const int wm   = warp & 1;    // 2 warps along M (64 rows each)
    const int wn   = warp >> 1;   // 4 warps along N (32 cols each)

    const int bm = blockIdx.y * BM;
    const int bn = blockIdx.x * BN;

    // ---- B dequant mapping: thread owns one n (tid&127) and 4 k-words ----
    const int b_n  = tid & 127;          // n within tile
    const int kw0  = tid >> 7;           // 0 or 1; kw = kw0 + 2*i
    const int n_g  = bn + b_n;           // global n for this thread's B work

    const __half2 off1032 = __halves2half2(__ushort_as_half((unsigned short)0x6408),
                                           __ushort_as_half((unsigned short)0x6408));

    float acc[4][4][4];
#pragma unroll
    for (int i = 0; i < 4; i++)
#pragma unroll
        for (int j = 0; j < 4; j++)
#pragma unroll
            for (int k = 0; k < 4; k++) acc[i][j][k] = 0.f;

    auto a_saddr = [&](int stage, int row, int colbytes) -> uint32_t {
        return smem_base + (uint32_t)((stage * STAGE_ELEMS + row * STRIDE) * 2) + colbytes;
    };
    auto b_saddr = [&](int stage, int row, int colbytes) -> uint32_t {
        return smem_base + (uint32_t)(((2 + stage) * STAGE_ELEMS + row * STRIDE) * 2) + colbytes;
    };

    uint32_t bw[4];
    __half   sc;

    // ---------- prologue ----------
    {
        // B stage 0 first: does NOT depend on cvt_x output (reads packed/scales only)
#pragma unroll
        for (int i = 0; i < 4; i++) {
            int kw = kw0 + 2 * i;
            bw[i] = (uint32_t)packed[(size_t)kw * NDIM + n_g];
        }
        sc = __float2half_rn(scales[n_g]);  // group 0
        __half2 sc2 = __half2half2(sc);
        uint32_t sbase = b_saddr(0, b_n, 0);
#pragma unroll
        for (int i = 0; i < 4; i++) {
            int kw = kw0 + 2 * i;
            uint32_t w = bw[i];
            uint32_t r[4];
#pragma unroll
            for (int j = 0; j < 4; j++) {
                uint32_t v = w >> (8 * j);
                uint32_t p = ((v & 0xFu) | ((v & 0xF0u) << 12)) | 0x64006400u;
                __half2 h = __hmul2(__hsub2(*(__half2*)&p, off1032), sc2);
                r[j] = *(uint32_t*)&h;
            }
            asm volatile("st.shared.v4.b32 [%0], {%1,%2,%3,%4};\n"
                         :: "r"(sbase + kw * 16), "r"(r[0]), "r"(r[1]), "r"(r[2]), "r"(r[3]));
        }

        // Now wait for cvt_x to fully complete before touching g_xh
        asm volatile("griddepcontrol.wait;" ::: "memory");

#pragma unroll
        for (int i = 0; i < 4; i++) {
            int c = tid + 256 * i;
            int row = c >> 3, cc = c & 7;
            cp_async16(a_saddr(0, row, cc * 16),
                       g_xh + (size_t)(bm + row) * KDIM + cc * 8);
        }
        cp_commit();
        cp_wait0();
        __syncthreads();
    }

    // ---------- main loop ----------
    const int arow  = wm * 64 + (lane & 15);
    const int acolg = (lane >> 4) * 8;
    const int brow  = wn * 32 + (lane & 15);

    for (int kt = 0; kt < NUM_KT; ++kt) {
        const int buf = kt & 1;
        const bool has_next = (kt + 1) < NUM_KT;

        if (has_next) {
            const int kb = (kt + 1) * BK;
#pragma unroll
            for (int i = 0; i < 4; i++) {
                int c = tid + 256 * i;
                int row = c >> 3, cc = c & 7;
                cp_async16(a_saddr(buf ^ 1, row, cc * 16),
                           g_xh + (size_t)(bm + row) * KDIM + kb + cc * 8);
            }
            cp_commit();
#pragma unroll
            for (int i = 0; i < 4; i++) {
                int kw = kw0 + 2 * i;
                bw[i] = (uint32_t)packed[(size_t)((kt + 1) * 8 + kw) * NDIM + n_g];
            }
            sc = __float2half_rn(scales[(size_t)((kt + 1) >> 1) * NDIM + n_g]);
        }

        // ---- compute from buf ----
        const uint32_t abase = smem_base + (uint32_t)(buf * STAGE_ELEMS * 2);
        const uint32_t bbase = smem_base + (uint32_t)((2 + buf) * STAGE_ELEMS * 2);
#pragma unroll
        for (int ks = 0; ks < 4; ks++) {
            uint32_t a[4][4];
#pragma unroll
            for (int mt = 0; mt < 4; mt++) {
                uint32_t addr = abase + (uint32_t)(((arow + mt * 16) * STRIDE + ks * 16 + acolg) * 2);
                ldmatrix_x4(a[mt][0], a[mt][1], a[mt][2], a[mt][3], addr);
            }
            uint32_t b[4][2];
#pragma unroll
            for (int nt2 = 0; nt2 < 2; nt2++) {
                uint32_t r0, r1, r2, r3;
                uint32_t addr = bbase + (uint32_t)(((brow + nt2 * 16) * STRIDE + ks * 16 + acolg) * 2);
                ldmatrix_x4(r0, r1, r2, r3, addr);
                b[2 * nt2][0] = r0; b[2 * nt2][1] = r2;
                b[2 * nt2 + 1][0] = r1; b[2 * nt2 + 1][1] = r3;
            }
#pragma unroll
            for (int mt = 0; mt < 4; mt++)
#pragma unroll
                for (int nt = 0; nt < 4; nt++)
                    mma16816(acc[mt][nt], a[mt], b[nt]);
        }

        if (has_next) {
            __half2 sc2 = __half2half2(sc);
            uint32_t sbase = b_saddr(buf ^ 1, b_n, 0);
#pragma unroll
            for (int i = 0; i < 4; i++) {
                int kw = kw0 + 2 * i;
                uint32_t w = bw[i];
                uint32_t r[4];
#pragma unroll
                for (int j = 0; j < 4; j++) {
                    uint32_t v = w >> (8 * j);
                    uint32_t p = ((v & 0xFu) | ((v & 0xF0u) << 12)) | 0x64006400u;
                    __half2 h = __hmul2(__hsub2(*(__half2*)&p, off1032), sc2);
                    r[j] = *(uint32_t*)&h;
                }
                asm volatile("st.shared.v4.b32 [%0], {%1,%2,%3,%4};\n"
                             :: "r"(sbase + kw * 16), "r"(r[0]), "r"(r[1]), "r"(r[2]), "r"(r[3]));
            }
            cp_wait0();
        }
        __syncthreads();
    }

    // ---------- epilogue: f32 out, rounded through fp16 to match reference ----------
#pragma unroll
    for (int mt = 0; mt < 4; mt++) {
#pragma unroll
        for (int nt = 0; nt < 4; nt++) {
            int row0 = bm + wm * 64 + mt * 16 + (lane >> 2);
            int col  = bn + wn * 32 + nt * 8 + (lane & 3) * 2;
            float2 bf = *(const float2*)(bias + col);
            float2 v0, v1;
            v0.x = __half2float(__float2half_rn(acc[mt][nt][0] + bf.x));
            v0.y = __half2float(__float2half_rn(acc[mt][nt][1] + bf.y));
            v1.x = __half2float(__float2half_rn(acc[mt][nt][2] + bf.x));
            v1.y = __half2float(__float2half_rn(acc[mt][nt][3] + bf.y));
            *(float2*)(out + (size_t)row0 * NDIM + col) = v0;
            *(float2*)(out + (size_t)(row0 + 8) * NDIM + col) = v1;
        }
    }
}

extern "C" void kernel_launch(void* const* d_in, const int* in_sizes, int n_in,
                              void* d_out, int out_size) {
    const float* x      = (const float*)d_in[0];
    const int*   packed = (const int*)d_in[1];
    const float* scales = (const float*)d_in[2];
    const float* bias   = (const float*)d_in[3];
    float*       out    = (float*)d_out;

    // prepass: x (f32) -> g_xh (fp16); signals dependents at entry
    const size_t n_x = (size_t)MDIM * KDIM;
    cvt_x_kernel<<<(unsigned)(n_x / 8 / 256), 256>>>(x);

    cudaFuncSetAttribute(qlinear_kernel, cudaFuncAttributeMaxDynamicSharedMemorySize, SMEM_BYTES);

    // GEMM launched as a programmatic dependent of cvt_x: its B-prologue
    // (packed/scales only) overlaps cvt_x's tail; griddepcontrol.wait guards g_xh.
    cudaLaunchConfig_t cfg = {};
    cfg.gridDim = dim3(NDIM / BN, MDIM / BM, 1);
    cfg.blockDim = dim3(256, 1, 1);
    cfg.dynamicSmemBytes = SMEM_BYTES;
    cfg.stream = 0;
    cudaLaunchAttribute attr[1];
    attr[0].id = cudaLaunchAttributeProgrammaticStreamSerialization;
    attr[0].val.programmaticStreamSerializationAllowed = 1;
    cfg.attrs = attr;
    cfg.numAttrs = 1;
    cudaLaunchKernelEx(&cfg, qlinear_kernel, packed, scales, bias, out);
}

// round 15
// speedup vs baseline: 1.0248x; 1.0244x over previous
#include <cuda_runtime.h>
#include <cuda_fp16.h>
#include <cstdint>

#define KDIM 4096
#define NDIM 11008
#define MDIM 4096
#define BM 128
#define BN 128
#define BK 64
#define STRIDE 72                 // padded row stride in halves (144 B)
#define STAGE_ELEMS (128 * STRIDE)
#define SMEM_BYTES (4 * STAGE_ELEMS * 2)   // A0,A1,B0,B1 = 73728 B -> 2 CTAs/SM
#define NUM_KT (KDIM / BK)        // 64

// fp16 copy of x (harness provides float32 for the reference's float16 tensors)
__device__ __half g_xh[(size_t)MDIM * KDIM];

// 8 floats per thread: 2x float4 load, 1x uint4 store
__global__ void cvt_x_kernel(const float* __restrict__ x) {
    asm volatile("griddepcontrol.launch_dependents;");
    size_t i = ((size_t)blockIdx.x * blockDim.x + threadIdx.x) * 8;
    float4 v0 = *(const float4*)(x + i);
    float4 v1 = *(const float4*)(x + i + 4);
    __half2 h0 = __floats2half2_rn(v0.x, v0.y);
    __half2 h1 = __floats2half2_rn(v0.z, v0.w);
    __half2 h2 = __floats2half2_rn(v1.x, v1.y);
    __half2 h3 = __floats2half2_rn(v1.z, v1.w);
    uint4 st;
    st.x = *(uint32_t*)&h0;
    st.y = *(uint32_t*)&h1;
    st.z = *(uint32_t*)&h2;
    st.w = *(uint32_t*)&h3;
    *(uint4*)(g_xh + i) = st;
}

__device__ __forceinline__ void cp_async16(uint32_t saddr, const void* gptr) {
    asm volatile("cp.async.cg.shared.global [%0], [%1], 16;\n" :: "r"(saddr), "l"(gptr));
}
__device__ __forceinline__ void cp_commit() { asm volatile("cp.async.commit_group;\n"); }
__device__ __forceinline__ void cp_wait0()  { asm volatile("cp.async.wait_group 0;\n"); }

__device__ __forceinline__ void ldmatrix_x4(uint32_t& r0, uint32_t& r1, uint32_t& r2, uint32_t& r3, uint32_t addr) {
    asm volatile("ldmatrix.sync.aligned.m8n8.x4.shared.b16 {%0,%1,%2,%3}, [%4];\n"
                 : "=r"(r0), "=r"(r1), "=r"(r2), "=r"(r3) : "r"(addr));
}

__device__ __forceinline__ void mma16816(float* d, const uint32_t* a, const uint32_t* b) {
    asm volatile(
        "mma.sync.aligned.m16n8k16.row.col.f32.f16.f16.f32 "
        "{%0,%1,%2,%3}, {%4,%5,%6,%7}, {%8,%9}, {%0,%1,%2,%3};\n"
        : "+f"(d[0]), "+f"(d[1]), "+f"(d[2]), "+f"(d[3])
        : "r"(a[0]), "r"(a[1]), "r"(a[2]), "r"(a[3]), "r"(b[0]), "r"(b[1]));
}

__global__ __launch_bounds__(256, 2)
void qlinear_kernel(const int*   __restrict__ packed,
                    const float* __restrict__ scales,
                    const float* __restrict__ bias,
                    float*       __restrict__ out)
{
    extern __shared__ __half smem[];
    const uint32_t smem_base = (uint32_t)__cvta_generic_to_shared(smem);

    const int tid  = threadIdx.x;
    const int lane = tid & 31;
    const int warp = tid >> 5;
    const int wm   = warp & 1;    // 2 warps along M (64 rows each)
    const int wn   = warp >> 1;   // 4 warps along N (32 cols each)

    const int bm = blockIdx.y * BM;
    const int bn = blockIdx.x * BN;

    // ---- B dequant mapping: thread owns one n (tid&127) and 4 k-words ----
    const int b_n  = tid & 127;          // n within tile
    const int kw0  = tid >> 7;           // 0 or 1; kw = kw0 + 2*i
    const int n_g  = bn + b_n;           // global n for this thread's B work

    const __half2 off1032 = __halves2half2(__ushort_as_half((unsigned short)0x6408),
                                           __ushort_as_half((unsigned short)0x6408));

    float acc[4][4][4];
#pragma unroll
    for (int i = 0; i < 4; i++)
#pragma unroll
        for (int j = 0; j < 4; j++)
#pragma unroll
            for (int k = 0; k < 4; k++) acc[i][j][k] = 0.f;

    auto a_saddr = [&](int stage, int row, int colbytes) -> uint32_t {
        return smem_base + (uint32_t)((stage * STAGE_ELEMS + row * STRIDE) * 2) + colbytes;
    };
    auto b_saddr = [&](int stage, int row, int colbytes) -> uint32_t {
        return smem_base + (uint32_t)(((2 + stage) * STAGE_ELEMS + row * STRIDE) * 2) + colbytes;
    };

    uint32_t bw[4];
    __half2  sc2;

    // ---------- prologue ----------
    {
        // B stage 0 first: independent of cvt_x output (packed/scales only)
#pragma unroll
        for (int i = 0; i < 4; i++) {
            int kw = kw0 + 2 * i;
            bw[i] = (uint32_t)packed[(size_t)kw * NDIM + n_g];
        }
        sc2 = __half2half2(__float2half_rn(scales[n_g]));   // group 0
        uint32_t sbase = b_saddr(0, b_n, 0);
#pragma unroll
        for (int i = 0; i < 4; i++) {
            int kw = kw0 + 2 * i;
            uint32_t w = bw[i];
            uint32_t r[4];
#pragma unroll
            for (int j = 0; j < 4; j++) {
                uint32_t v = w >> (8 * j);
                uint32_t p = ((v & 0xFu) | ((v & 0xF0u) << 12)) | 0x64006400u;
                __half2 h = __hmul2(__hsub2(*(__half2*)&p, off1032), sc2);
                r[j] = *(uint32_t*)&h;
            }
            asm volatile("st.shared.v4.b32 [%0], {%1,%2,%3,%4};\n"
                         :: "r"(sbase + kw * 16), "r"(r[0]), "r"(r[1]), "r"(r[2]), "r"(r[3]));
        }

        // wait for cvt_x before touching g_xh
        asm volatile("griddepcontrol.wait;" ::: "memory");

#pragma unroll
        for (int i = 0; i < 4; i++) {
            int c = tid + 256 * i;
            int row = c >> 3, cc = c & 7;
            cp_async16(a_saddr(0, row, cc * 16),
                       g_xh + (size_t)(bm + row) * KDIM + cc * 8);
        }
        cp_commit();
        cp_wait0();
        __syncthreads();
    }

    // ---------- main loop ----------
    const int arow  = wm * 64 + (lane & 15);
    const int acolg = (lane >> 4) * 8;
    const int brow  = wn * 32 + (lane & 15);

#pragma unroll 2
    for (int kt = 0; kt < NUM_KT; ++kt) {
        const int buf = kt & 1;
        const bool has_next = (kt + 1) < NUM_KT;

        if (has_next) {
            const int kb = (kt + 1) * BK;
#pragma unroll
            for (int i = 0; i < 4; i++) {
                int c = tid + 256 * i;
                int row = c >> 3, cc = c & 7;
                cp_async16(a_saddr(buf ^ 1, row, cc * 16),
                           g_xh + (size_t)(bm + row) * KDIM + kb + cc * 8);
            }
            cp_commit();
#pragma unroll
            for (int i = 0; i < 4; i++) {
                int kw = kw0 + 2 * i;
                bw[i] = (uint32_t)packed[(size_t)((kt + 1) * 8 + kw) * NDIM + n_g];
            }
            // scale group changes only at even kt+1 (group = (kt+1)>>1)
            if (((kt + 1) & 1) == 0)
                sc2 = __half2half2(__float2half_rn(scales[(size_t)((kt + 1) >> 1) * NDIM + n_g]));
        }

        // ---- compute from buf ----
        const uint32_t abase = smem_base + (uint32_t)(buf * STAGE_ELEMS * 2);
        const uint32_t bbase = smem_base + (uint32_t)((2 + buf) * STAGE_ELEMS * 2);
#pragma unroll
        for (int ks = 0; ks < 4; ks++) {
            uint32_t a[4][4];
#pragma unroll
            for (int mt = 0; mt < 4; mt++) {
                uint32_t addr = abase + (uint32_t)(((arow + mt * 16) * STRIDE + ks * 16 + acolg) * 2);
                ldmatrix_x4(a[mt][0], a[mt][1], a[mt][2], a[mt][3], addr);
            }
            uint32_t b[4][2];
#pragma unroll
            for (int nt2 = 0; nt2 < 2; nt2++) {
                uint32_t r0, r1, r2, r3;
                uint32_t addr = bbase + (uint32_t)(((brow + nt2 * 16) * STRIDE + ks * 16 + acolg) * 2);
                ldmatrix_x4(r0, r1, r2, r3, addr);
                b[2 * nt2][0] = r0; b[2 * nt2][1] = r2;
                b[2 * nt2 + 1][0] = r1; b[2 * nt2 + 1][1] = r3;
            }
#pragma unroll
            for (int mt = 0; mt < 4; mt++)
#pragma unroll
                for (int nt = 0; nt < 4; nt++)
                    mma16816(acc[mt][nt], a[mt], b[nt]);
        }

        if (has_next) {
            uint32_t sbase = b_saddr(buf ^ 1, b_n, 0);
#pragma unroll
            for (int i = 0; i < 4; i++) {
                int kw = kw0 + 2 * i;
                uint32_t w = bw[i];
                uint32_t r[4];
#pragma unroll
                for (int j = 0; j < 4; j++) {
                    uint32_t v = w >> (8 * j);
                    uint32_t p = ((v & 0xFu) | ((v & 0xF0u) << 12)) | 0x64006400u;
                    __half2 h = __hmul2(__hsub2(*(__half2*)&p, off1032), sc2);
                    r[j] = *(uint32_t*)&h;
                }
                asm volatile("st.shared.v4.b32 [%0], {%1,%2,%3,%4};\n"
                             :: "r"(sbase + kw * 16), "r"(r[0]), "r"(r[1]), "r"(r[2]), "r"(r[3]));
            }
            cp_wait0();
        }
        __syncthreads();
    }

    // ---------- epilogue: f32 out, rounded through fp16 to match reference ----------
#pragma unroll
    for (int mt = 0; mt < 4; mt++) {
#pragma unroll
        for (int nt = 0; nt < 4; nt++) {
            int row0 = bm + wm * 64 + mt * 16 + (lane >> 2);
            int col  = bn + wn * 32 + nt * 8 + (lane & 3) * 2;
            float2 bf = *(const float2*)(bias + col);
            float2 v0, v1;
            v0.x = __half2float(__float2half_rn(acc[mt][nt][0] + bf.x));
            v0.y = __half2float(__float2half_rn(acc[mt][nt][1] + bf.y));
            v1.x = __half2float(__float2half_rn(acc[mt][nt][2] + bf.x));
            v1.y = __half2float(__float2half_rn(acc[mt][nt][3] + bf.y));
            *(float2*)(out + (size_t)row0 * NDIM + col) = v0;
            *(float2*)(out + (size_t)(row0 + 8) * NDIM + col) = v1;
        }
    }
}

extern "C" void kernel_launch(void* const* d_in, const int* in_sizes, int n_in,
                              void* d_out, int out_size) {
    const float* x      = (const float*)d_in[0];
    const int*   packed = (const int*)d_in[1];
    const float* scales = (const float*)d_in[2];
    const float* bias   = (const float*)d_in[3];
    float*       out    = (float*)d_out;

    // prepass: x (f32) -> g_xh (fp16); signals dependents at entry
    const size_t n_x = (size_t)MDIM * KDIM;
    cvt_x_kernel<<<(unsigned)(n_x / 8 / 256), 256>>>(x);

    cudaFuncSetAttribute(qlinear_kernel, cudaFuncAttributeMaxDynamicSharedMemorySize, SMEM_BYTES);

    // GEMM launched as programmatic dependent of cvt_x (PDL): B-prologue overlaps
    // cvt_x tail; griddepcontrol.wait guards g_xh reads.
    cudaLaunchConfig_t cfg = {};
    cfg.gridDim = dim3(NDIM / BN, MDIM / BM, 1);
    cfg.blockDim = dim3(256, 1, 1);
    cfg.dynamicSmemBytes = SMEM_BYTES;
    cfg.stream = 0;
    cudaLaunchAttribute attr[1];
    attr[0].id = cudaLaunchAttributeProgrammaticStreamSerialization;
    attr[0].val.programmaticStreamSerializationAllowed = 1;
    cfg.attrs = attr;
    cfg.numAttrs = 1;
    cudaLaunchKernelEx(&cfg, qlinear_kernel, packed, scales, bias, out);
}